// round 16
// baseline (speedup 1.0000x reference)
#include <cuda_runtime.h>
#include <cuda_fp16.h>
#include <cstdint>
#include <cstddef>

#define D_IN  256
#define D_OUT 128
#define MAX_N 100000
#define MAX_E 1600000
#define SCAN_BLK 1024
#define VALID_FLAG (1u << 30)

// Scratch (device globals: no allocation allowed)
__device__ uint32_t g_hh[(size_t)MAX_N * (D_OUT / 2)];  // h as fp16x2, 25.6 MB
__device__ float  g_a1[MAX_N];
__device__ float  g_a2[MAX_N];
__device__ __half g_Wth[D_OUT * D_IN];          // W transposed, fp16 [n][k]
__device__ int    g_count[MAX_N];
__device__ unsigned g_bsum[128];                // block totals | VALID_FLAG
__device__ int    g_rowstart[MAX_N + 1];
__device__ int    g_pos[MAX_N];
__device__ int2   g_src[MAX_E];                 // CSR-position-ordered (row, col)
__device__ float2 g_scw[MAX_E];                 // packed (col-as-float-bits, expw)

// ---------------- ldmatrix / mma / cp.async wrappers ----------------
__device__ __forceinline__ uint32_t smem_u32(const void* p) {
    return (uint32_t)__cvta_generic_to_shared(p);
}
__device__ __forceinline__ void ldsm_x4(uint32_t& r0, uint32_t& r1,
                                        uint32_t& r2, uint32_t& r3, uint32_t addr) {
    asm volatile("ldmatrix.sync.aligned.m8n8.x4.shared.b16 {%0,%1,%2,%3}, [%4];"
                 : "=r"(r0), "=r"(r1), "=r"(r2), "=r"(r3) : "r"(addr));
}
__device__ __forceinline__ void mma_f16(float* d, const uint32_t* a,
                                        uint32_t b0, uint32_t b1) {
    asm volatile(
        "mma.sync.aligned.m16n8k16.row.col.f32.f16.f16.f32 "
        "{%0,%1,%2,%3}, {%4,%5,%6,%7}, {%8,%9}, {%0,%1,%2,%3};"
        : "+f"(d[0]), "+f"(d[1]), "+f"(d[2]), "+f"(d[3])
        : "r"(a[0]), "r"(a[1]), "r"(a[2]), "r"(a[3]), "r"(b0), "r"(b1));
}
__device__ __forceinline__ uint32_t f16x2_rn(float lo, float hi) {
    uint32_t r;   // %1 -> high half, %2 -> low half
    asm("cvt.rn.f16x2.f32 %0, %1, %2;" : "=r"(r) : "f"(hi), "f"(lo));
    return r;
}
__device__ __forceinline__ void cp_async16(uint32_t dst, const void* src, int src_bytes) {
    asm volatile("cp.async.cg.shared.global [%0], [%1], 16, %2;"
                 :: "r"(dst), "l"(src), "r"(src_bytes));
}
__device__ __forceinline__ void cp_commit() {
    asm volatile("cp.async.commit_group;");
}
template <int N>
__device__ __forceinline__ void cp_wait() {
    asm volatile("cp.async.wait_group %0;" :: "n"(N));
}

// ---------------- transpose W -> fp16 [n][k] --------------------------------
__global__ void __launch_bounds__(256) transpose_w_kernel(const float* __restrict__ W)
{
    int idx = blockIdx.x * 256 + threadIdx.x;   // 32768 total
    if (idx < D_IN * D_OUT) {
        int k = idx / D_OUT;
        int n = idx % D_OUT;
        g_Wth[n * D_IN + k] = __float2half_rn(W[idx]);
    }
}

// ---------------- fp16 tensor-core GEMM (m16n8k16), B fully resident --------
// h = X@W + b -> fp16; fused a1 = h@wa1+ba1, a2 = h@wa2+ba2 (smem exchange).
// All 8 B k-tiles loaded ONCE per CTA (64KB fp16); loop only streams A.
#define APAD    40                      // halves per row (80B, conflict-free ldsm)
#define A_TILE_H (128 * APAD)           // halves per A stage
#define B_TILE_H (128 * APAD)           // halves per B tile
#define NKT     (D_IN / 32)             // 8 k-tiles

__global__ void __launch_bounds__(256) gemm_f16_kernel(
    const float* __restrict__ A,
    const float* __restrict__ bias,
    const float* __restrict__ wa1, const float* __restrict__ wa2,
    const float* __restrict__ ba1, const float* __restrict__ ba2,
    int M)
{
    extern __shared__ __half smh[];
    __half* AH = smh;                   // 2 A stages
    __half* BH = smh + 2 * A_TILE_H;    // 8 B tiles (whole W)

    const int tid  = threadIdx.x;
    const int lane = tid & 31;
    const int wid  = tid >> 5;
    const int wm   = wid & 3;
    const int wn   = wid >> 2;
    const int row0 = blockIdx.x * 128;
    const int mrow = wm * 32;
    const int ncol = wn * 64;

    // A load coords: 4 float4 per thread (128 rows x 32 k fp32 per tile)
    int lr[4], lc[4];
#pragma unroll
    for (int i = 0; i < 4; i++) {
        int idx = tid + i * 256;
        lr[i] = idx >> 3;        // row 0..127
        lc[i] = (idx & 7) * 4;   // k offset 0..28
    }

    // ---- load ALL of B once: 8 tiles x 128 rows x 4 chunks = 4096 chunks ----
#pragma unroll
    for (int i = 0; i < 16; i++) {
        int idx = tid + i * 256;        // 0..4095
        int tile = idx >> 9;            // 0..7
        int r    = (idx >> 2) & 127;    // n row
        int ck   = (idx & 3) * 8;       // k offset in halves
        const __half* src = g_Wth + (size_t)r * D_IN + tile * 32 + ck;
        cp_async16(smem_u32(BH + tile * B_TILE_H + r * APAD + ck), src, 16);
    }
    cp_commit();

    auto load_a_regs = [&](int k0, float4* pre) {
#pragma unroll
        for (int i = 0; i < 4; i++) {
            int gr = row0 + lr[i];
            pre[i] = (gr < M)
                ? *reinterpret_cast<const float4*>(A + (size_t)gr * D_IN + k0 + lc[i])
                : make_float4(0.f, 0.f, 0.f, 0.f);
        }
    };

    float c[2][8][4];
#pragma unroll
    for (int mt = 0; mt < 2; mt++)
#pragma unroll
        for (int nt = 0; nt < 8; nt++)
#pragma unroll
            for (int i = 0; i < 4; i++) c[mt][nt][i] = 0.f;

    float4 pre[4];
    load_a_regs(0, pre);
    cp_wait<0>();                        // B resident from here on

    for (int kt = 0; kt < NKT; kt++) {
        const int s = kt & 1;
        // store prefetched A (converted to fp16) into stage s.
        // Safe: stage s was last READ at iter kt-2; every warp passed the
        // barrier of iter kt-1 only after finishing those reads.
        __half* Ad = AH + s * A_TILE_H;
#pragma unroll
        for (int i = 0; i < 4; i++) {
            uint2 v;
            v.x = f16x2_rn(pre[i].x, pre[i].y);
            v.y = f16x2_rn(pre[i].z, pre[i].w);
            *reinterpret_cast<uint2*>(Ad + lr[i] * APAD + lc[i]) = v;
        }
        // prefetch next A tile into regs (latency hidden by compute below)
        if (kt + 1 < NKT) load_a_regs((kt + 1) * 32, pre);

        __syncthreads();                 // single barrier per k-tile

        const __half* As = AH + s * A_TILE_H;
        const __half* Bt = BH + kt * B_TILE_H;

#pragma unroll
        for (int ks = 0; ks < 32; ks += 16) {
            uint32_t a[2][4];
#pragma unroll
            for (int mt = 0; mt < 2; mt++) {
                uint32_t addr = smem_u32(
                    As + (mrow + mt * 16 + (lane & 7) + 8 * ((lane >> 3) & 1)) * APAD
                       + ks + 8 * (lane >> 4));
                ldsm_x4(a[mt][0], a[mt][1], a[mt][2], a[mt][3], addr);
            }
            uint32_t b[8][2];
#pragma unroll
            for (int p = 0; p < 4; p++) {
                uint32_t r0, r1, r2, r3;
                uint32_t addr = smem_u32(
                    Bt + (ncol + p * 16 + (lane & 7) + 8 * ((lane >> 3) & 1)) * APAD
                       + ks + 8 * (lane >> 4));
                ldsm_x4(r0, r1, r2, r3, addr);
                b[2 * p][0]     = r0; b[2 * p][1]     = r2;
                b[2 * p + 1][0] = r1; b[2 * p + 1][1] = r3;
            }
#pragma unroll
            for (int mt = 0; mt < 2; mt++)
#pragma unroll
                for (int nt = 0; nt < 8; nt++)
                    mma_f16(c[mt][nt], a[mt], b[nt][0], b[nt][1]);
        }
    }

    // ---------------- epilogue: fp16 h store + a1/a2 via smem exchange ------
    __syncthreads();    // guard smem reuse (all warps done reading tiles)
    float* sp1 = reinterpret_cast<float*>(smh);         // [128]
    float* sp2 = reinterpret_cast<float*>(smh) + 128;   // [128]

    const float ba1v = ba1[0];
    const float ba2v = ba2[0];
    const int qrow = lane >> 2;
    const int qcol = 2 * (lane & 3);

    float P1[2][2], P2[2][2];   // [mt][lo/hi]

#pragma unroll
    for (int mt = 0; mt < 2; mt++) {
        int grlo = row0 + mrow + mt * 16 + qrow;
        int grhi = grlo + 8;
        float p1lo = 0.f, p2lo = 0.f, p1hi = 0.f, p2hi = 0.f;
#pragma unroll
        for (int nt = 0; nt < 8; nt++) {
            int gc = ncol + nt * 8 + qcol;
            float bc0 = bias[gc], bc1 = bias[gc + 1];
            float v0 = c[mt][nt][0] + bc0;
            float v1 = c[mt][nt][1] + bc1;
            float v2 = c[mt][nt][2] + bc0;
            float v3 = c[mt][nt][3] + bc1;
            if (grlo < M)
                g_hh[(size_t)grlo * (D_OUT / 2) + gc / 2] = f16x2_rn(v0, v1);
            if (grhi < M)
                g_hh[(size_t)grhi * (D_OUT / 2) + gc / 2] = f16x2_rn(v2, v3);
            float w1a = wa1[gc], w1b = wa1[gc + 1];
            float w2a = wa2[gc], w2b = wa2[gc + 1];
            p1lo += v0 * w1a + v1 * w1b;
            p2lo += v0 * w2a + v1 * w2b;
            p1hi += v2 * w1a + v3 * w1b;
            p2hi += v2 * w2a + v3 * w2b;
        }
#pragma unroll
        for (int o = 1; o < 4; o <<= 1) {
            p1lo += __shfl_xor_sync(0xffffffffu, p1lo, o);
            p2lo += __shfl_xor_sync(0xffffffffu, p2lo, o);
            p1hi += __shfl_xor_sync(0xffffffffu, p1hi, o);
            p2hi += __shfl_xor_sync(0xffffffffu, p2hi, o);
        }
        P1[mt][0] = p1lo; P1[mt][1] = p1hi;
        P2[mt][0] = p2lo; P2[mt][1] = p2hi;
    }

    // wn=1 publishes partials; wn=0 combines and stores (no atomics)
    if (wn == 1 && (lane & 3) == 0) {
#pragma unroll
        for (int mt = 0; mt < 2; mt++) {
            int lrow = mrow + mt * 16 + qrow;
            sp1[lrow]     = P1[mt][0];  sp2[lrow]     = P2[mt][0];
            sp1[lrow + 8] = P1[mt][1];  sp2[lrow + 8] = P2[mt][1];
        }
    }
    __syncthreads();
    if (wn == 0 && (lane & 3) == 0) {
#pragma unroll
        for (int mt = 0; mt < 2; mt++) {
            int lrow = mrow + mt * 16 + qrow;
            int grlo = row0 + lrow, grhi = grlo + 8;
            if (grlo < M) {
                g_a1[grlo] = P1[mt][0] + sp1[lrow] + ba1v;
                g_a2[grlo] = P2[mt][0] + sp2[lrow] + ba2v;
            }
            if (grhi < M) {
                g_a1[grhi] = P1[mt][1] + sp1[lrow + 8] + ba1v;
                g_a2[grhi] = P2[mt][1] + sp2[lrow + 8] + ba2v;
            }
        }
    }
}

// ---------------- histogram of destination rows (also zeros g_bsum) ---------
__global__ void __launch_bounds__(256) hist_kernel(
    const int* __restrict__ row, int E)
{
    if (blockIdx.x == 0 && threadIdx.x < 128)
        g_bsum[threadIdx.x] = 0;

    int t = blockIdx.x * blockDim.x + threadIdx.x;
    int nq = E >> 2;
    if (t < nq) {
        int4 v = reinterpret_cast<const int4*>(row)[t];
        atomicAdd(&g_count[v.x], 1);
        atomicAdd(&g_count[v.y], 1);
        atomicAdd(&g_count[v.z], 1);
        atomicAdd(&g_count[v.w], 1);
    }
    int rem = nq * 4 + t;
    if (t < (E & 3) && rem < E) atomicAdd(&g_count[row[rem]], 1);
}

// ---------------- fused single-pass exclusive scan (inter-block lookback) ----
__device__ __forceinline__ void block_scan_1024(int v, int tid, int& excl, int& total)
{
    int lane = tid & 31, wid = tid >> 5;
    int x = v;
#pragma unroll
    for (int o = 1; o < 32; o <<= 1) {
        int y = __shfl_up_sync(0xffffffffu, x, o);
        if (lane >= o) x += y;
    }
    __shared__ int ws[32];
    if (lane == 31) ws[wid] = x;
    __syncthreads();
    if (wid == 0) {
        int s = ws[lane];
#pragma unroll
        for (int o = 1; o < 32; o <<= 1) {
            int y = __shfl_up_sync(0xffffffffu, s, o);
            if (lane >= o) s += y;
        }
        ws[lane] = s;
    }
    __syncthreads();
    int warp_off = (wid > 0) ? ws[wid - 1] : 0;
    int incl = warp_off + x;
    excl  = incl - v;
    total = ws[31];
}

__global__ void __launch_bounds__(SCAN_BLK) scan_fused_kernel(int n, int E)
{
    int i = blockIdx.x * SCAN_BLK + threadIdx.x;
    int v = (i < n) ? g_count[i] : 0;
    int excl, total;
    block_scan_1024(v, threadIdx.x, excl, total);

    if (threadIdx.x == 0)
        atomicExch(&g_bsum[blockIdx.x], (unsigned)total | VALID_FLAG);

    int part = 0;
    if (threadIdx.x < blockIdx.x) {
        unsigned w;
        do { w = atomicAdd(&g_bsum[threadIdx.x], 0u); } while (!(w & VALID_FLAG));
        part = (int)(w & (VALID_FLAG - 1));
    }
    int lane = threadIdx.x & 31, wid = threadIdx.x >> 5;
#pragma unroll
    for (int o = 16; o > 0; o >>= 1)
        part += __shfl_xor_sync(0xffffffffu, part, o);
    __shared__ int rs[32];
    __syncthreads();
    if (lane == 0) rs[wid] = part;
    __syncthreads();
    if (wid == 0) {
        int s = rs[lane];
#pragma unroll
        for (int o = 16; o > 0; o >>= 1)
            s += __shfl_xor_sync(0xffffffffu, s, o);
        rs[0] = s;
    }
    __syncthreads();
    int offset = rs[0];

    if (i < n) {
        int vv = excl + offset;
        g_rowstart[i] = vv;
        g_pos[i]      = vv;
        if (i == n - 1) g_rowstart[n] = E;
    }
}

// ---------------- CSR (row,col) scatter — NO scores, runs in fork -----------
__global__ void __launch_bounds__(256) scatter_rc_kernel(
    const int* __restrict__ row, const int* __restrict__ col, int E)
{
    int e = blockIdx.x * blockDim.x + threadIdx.x;
    if (e < E) {
        int r = row[e];
        int p = atomicAdd(&g_pos[r], 1);
        g_src[p] = make_int2(r, col[e]);
    }
}

// ---------------- score pass: coalesced over CSR positions ------------------
__global__ void __launch_bounds__(256) score_kernel(int E)
{
    int p = blockIdx.x * blockDim.x + threadIdx.x;
    if (p < E) {
        int2 rc = g_src[p];
        float s = g_a1[rc.x] + g_a2[rc.y];
        s = (s > 0.f) ? s : 0.01f * s;       // LeakyReLU(0.01)
        float w = __expf(s);                  // exp(s)/sum == softmax
        g_scw[p] = make_float2(__int_as_float(rc.y), w);
    }
}

// ---------------- CSR gather SpMM: one warp per row, fp16 h ----------------
__device__ __forceinline__ void f16x2_unpack(uint32_t u, float& lo, float& hi) {
    __half2 h = *reinterpret_cast<__half2*>(&u);
    float2 f = __half22float2(h);
    lo = f.x;
    hi = f.y;
}

__global__ void __launch_bounds__(256) spmm_csr_kernel(
    float* __restrict__ out, int M)
{
    int r    = (blockIdx.x * blockDim.x + threadIdx.x) >> 5;
    int lane = threadIdx.x & 31;
    if (r >= M) return;

    int start = g_rowstart[r];
    int end   = g_rowstart[r + 1];

    float4 acc = make_float4(0.f, 0.f, 0.f, 0.f);

    if (end > start) {
        const uint2* __restrict__ h2 = reinterpret_cast<const uint2*>(g_hh);
        float dsum = 0.f;   // identical in every lane

        for (int base = start; base < end; base += 32) {
            int   i = base + lane;
            int   cc = 0;
            float ww = 0.f;
            if (i < end) {
                float2 e = g_scw[i];
                cc = __float_as_int(e.x);
                ww = e.y;
            }
            int n = end - base; if (n > 32) n = 32;

            int j = 0;
            for (; j + 4 <= n; j += 4) {
                int   c0 = __shfl_sync(0xffffffffu, cc, j);
                int   c1 = __shfl_sync(0xffffffffu, cc, j + 1);
                int   c2 = __shfl_sync(0xffffffffu, cc, j + 2);
                int   c3 = __shfl_sync(0xffffffffu, cc, j + 3);
                float w0 = __shfl_sync(0xffffffffu, ww, j);
                float w1 = __shfl_sync(0xffffffffu, ww, j + 1);
                float w2 = __shfl_sync(0xffffffffu, ww, j + 2);
                float w3 = __shfl_sync(0xffffffffu, ww, j + 3);
                uint2 u0 = h2[(size_t)c0 * 32 + lane];
                uint2 u1 = h2[(size_t)c1 * 32 + lane];
                uint2 u2 = h2[(size_t)c2 * 32 + lane];
                uint2 u3 = h2[(size_t)c3 * 32 + lane];
                dsum += w0 + w1 + w2 + w3;
                float ax, ay, az, aw;
                f16x2_unpack(u0.x, ax, ay); f16x2_unpack(u0.y, az, aw);
                acc.x = fmaf(w0, ax, acc.x); acc.y = fmaf(w0, ay, acc.y);
                acc.z = fmaf(w0, az, acc.z); acc.w = fmaf(w0, aw, acc.w);
                f16x2_unpack(u1.x, ax, ay); f16x2_unpack(u1.y, az, aw);
                acc.x = fmaf(w1, ax, acc.x); acc.y = fmaf(w1, ay, acc.y);
                acc.z = fmaf(w1, az, acc.z); acc.w = fmaf(w1, aw, acc.w);
                f16x2_unpack(u2.x, ax, ay); f16x2_unpack(u2.y, az, aw);
                acc.x = fmaf(w2, ax, acc.x); acc.y = fmaf(w2, ay, acc.y);
                acc.z = fmaf(w2, az, acc.z); acc.w = fmaf(w2, aw, acc.w);
                f16x2_unpack(u3.x, ax, ay); f16x2_unpack(u3.y, az, aw);
                acc.x = fmaf(w3, ax, acc.x); acc.y = fmaf(w3, ay, acc.y);
                acc.z = fmaf(w3, az, acc.z); acc.w = fmaf(w3, aw, acc.w);
            }
            for (; j < n; j++) {
                int   cj = __shfl_sync(0xffffffffu, cc, j);
                float wj = __shfl_sync(0xffffffffu, ww, j);
                uint2 u = h2[(size_t)cj * 32 + lane];
                dsum += wj;
                float ax, ay, az, aw;
                f16x2_unpack(u.x, ax, ay); f16x2_unpack(u.y, az, aw);
                acc.x = fmaf(wj, ax, acc.x); acc.y = fmaf(wj, ay, acc.y);
                acc.z = fmaf(wj, az, acc.z); acc.w = fmaf(wj, aw, acc.w);
            }
        }
        float inv = 1.0f / dsum;
        acc.x *= inv; acc.y *= inv; acc.z *= inv; acc.w *= inv;
    }
    *reinterpret_cast<float4*>(out + (size_t)r * D_OUT + lane * 4) = acc;
}

// ---------------- launch: fork starts immediately; transpose on main --------
extern "C" void kernel_launch(void* const* d_in, const int* in_sizes, int n_in,
                              void* d_out, int out_size)
{
    const float* features = (const float*)d_in[0];
    const int*   ei       = (const int*)d_in[1];
    const float* W        = (const float*)d_in[2];
    const float* b        = (const float*)d_in[3];
    const float* wa1      = (const float*)d_in[4];
    const float* ba1      = (const float*)d_in[5];
    const float* wa2      = (const float*)d_in[6];
    const float* ba2      = (const float*)d_in[7];

    const int M = in_sizes[0] / D_IN;   // 100000
    const int E = in_sizes[1] / 2;      // 1600000
    float* out = (float*)d_out;

    const int* rowp = ei;
    const int* colp = ei + E;

    // lazily created once on the (uncaptured) correctness call; reused during capture
    static cudaStream_t s1 = nullptr;
    static cudaEvent_t  evFork = nullptr, evJoin = nullptr;
    if (s1 == nullptr) {
        cudaStreamCreateWithFlags(&s1, cudaStreamNonBlocking);
        cudaEventCreateWithFlags(&evFork, cudaEventDisableTiming);
        cudaEventCreateWithFlags(&evJoin, cudaEventDisableTiming);
    }

    void* p = nullptr;

    // fork FIRST: s1 must not wait on the transpose
    cudaEventRecord(evFork, 0);
    cudaStreamWaitEvent(s1, evFork, 0);

    // s1: CSR structure build (independent of GEMM, low bandwidth)
    cudaGetSymbolAddress(&p, g_count);
    cudaMemsetAsync(p, 0, (size_t)M * sizeof(int), s1);
    hist_kernel<<<(E / 4 + 255) / 256, 256, 0, s1>>>(rowp, E);  // also zeros g_bsum
    int nb = (M + SCAN_BLK - 1) / SCAN_BLK;
    scan_fused_kernel<<<nb, SCAN_BLK, 0, s1>>>(M, E);
    int eblocks = (E + 255) / 256;
    scatter_rc_kernel<<<eblocks, 256, 0, s1>>>(rowp, colp, E);
    cudaEventRecord(evJoin, s1);

    // main stream: W transpose + GEMM (writes a1/a2 directly)
    transpose_w_kernel<<<(D_IN * D_OUT + 255) / 256, 256>>>(W);

    static const size_t smem_bytes = (2 * A_TILE_H + 8 * B_TILE_H) * sizeof(__half); // 102400
    cudaFuncSetAttribute(gemm_f16_kernel,
                         cudaFuncAttributeMaxDynamicSharedMemorySize,
                         (int)smem_bytes);
    int gblocks = (M + 127) / 128;
    gemm_f16_kernel<<<gblocks, 256, smem_bytes>>>(features, b, wa1, wa2, ba1, ba2, M);

    // join: score needs g_src (s1) + a1/a2 (main)
    cudaStreamWaitEvent(0, evJoin, 0);

    score_kernel<<<eblocks, 256>>>(E);

    long long total_threads = (long long)M * 32;
    int mblocks = (int)((total_threads + 255) / 256);
    spmm_csr_kernel<<<mblocks, 256>>>(out, M);
}

// round 17
// speedup vs baseline: 1.1472x; 1.1472x over previous
#include <cuda_runtime.h>
#include <cuda_fp16.h>
#include <cstdint>
#include <cstddef>

#define D_IN  256
#define D_OUT 128
#define MAX_N 100000
#define MAX_E 1600000
#define SCAN_BLK 1024
#define VALID_FLAG (1u << 30)

// Scratch (device globals: no allocation allowed)
__device__ uint32_t g_hh[(size_t)MAX_N * (D_OUT / 2)];  // h as fp16x2, 25.6 MB
__device__ float  g_a1[MAX_N];
__device__ float  g_a2[MAX_N];
__device__ __half g_Wth[D_OUT * D_IN];          // W transposed, fp16 [n][k]
__device__ int    g_count[MAX_N];
__device__ unsigned g_bsum[128];                // block totals | VALID_FLAG
__device__ int    g_rowstart[MAX_N + 1];
__device__ int    g_pos[MAX_N];
__device__ int2   g_src[MAX_E];                 // CSR-position-ordered (row, col)
__device__ float2 g_scw[MAX_E];                 // packed (col-as-float-bits, expw)

// ---------------- ldmatrix / mma / cp.async wrappers ----------------
__device__ __forceinline__ uint32_t smem_u32(const void* p) {
    return (uint32_t)__cvta_generic_to_shared(p);
}
__device__ __forceinline__ void ldsm_x4(uint32_t& r0, uint32_t& r1,
                                        uint32_t& r2, uint32_t& r3, uint32_t addr) {
    asm volatile("ldmatrix.sync.aligned.m8n8.x4.shared.b16 {%0,%1,%2,%3}, [%4];"
                 : "=r"(r0), "=r"(r1), "=r"(r2), "=r"(r3) : "r"(addr));
}
__device__ __forceinline__ void mma_f16(float* d, const uint32_t* a,
                                        uint32_t b0, uint32_t b1) {
    asm volatile(
        "mma.sync.aligned.m16n8k16.row.col.f32.f16.f16.f32 "
        "{%0,%1,%2,%3}, {%4,%5,%6,%7}, {%8,%9}, {%0,%1,%2,%3};"
        : "+f"(d[0]), "+f"(d[1]), "+f"(d[2]), "+f"(d[3])
        : "r"(a[0]), "r"(a[1]), "r"(a[2]), "r"(a[3]), "r"(b0), "r"(b1));
}
__device__ __forceinline__ uint32_t f16x2_rn(float lo, float hi) {
    uint32_t r;   // %1 -> high half, %2 -> low half
    asm("cvt.rn.f16x2.f32 %0, %1, %2;" : "=r"(r) : "f"(hi), "f"(lo));
    return r;
}
__device__ __forceinline__ void cp_async16(uint32_t dst, const void* src, int src_bytes) {
    asm volatile("cp.async.cg.shared.global [%0], [%1], 16, %2;"
                 :: "r"(dst), "l"(src), "r"(src_bytes));
}
__device__ __forceinline__ void cp_commit() {
    asm volatile("cp.async.commit_group;");
}
template <int N>
__device__ __forceinline__ void cp_wait() {
    asm volatile("cp.async.wait_group %0;" :: "n"(N));
}

// ---------------- transpose W -> fp16 [n][k] --------------------------------
__global__ void __launch_bounds__(256) transpose_w_kernel(const float* __restrict__ W)
{
    int idx = blockIdx.x * 256 + threadIdx.x;   // 32768 total
    if (idx < D_IN * D_OUT) {
        int k = idx / D_OUT;
        int n = idx % D_OUT;
        g_Wth[n * D_IN + k] = __float2half_rn(W[idx]);
    }
}

// ---------------- fp16 tensor-core GEMM (m16n8k16) --------------------------
// h = X@W + b -> fp16; fused a1 = h@wa1+ba1, a2 = h@wa2+ba2 (smem exchange,
// no atomics, no memsets). Single barrier per k-tile. (R15 configuration.)
#define APAD    40                      // halves per row (80B, conflict-free ldsm)
#define A_TILE_H (128 * APAD)           // halves per A stage
#define B_TILE_H (128 * APAD)           // halves per B stage
#define NKT     (D_IN / 32)             // 8 k-tiles

__global__ void __launch_bounds__(256) gemm_f16_kernel(
    const float* __restrict__ A,
    const float* __restrict__ bias,
    const float* __restrict__ wa1, const float* __restrict__ wa2,
    const float* __restrict__ ba1, const float* __restrict__ ba2,
    int M)
{
    extern __shared__ __half smh[];
    __half* AH = smh;                   // 2 stages
    __half* BH = smh + 2 * A_TILE_H;    // 3 stages

    const int tid  = threadIdx.x;
    const int lane = tid & 31;
    const int wid  = tid >> 5;
    const int wm   = wid & 3;
    const int wn   = wid >> 2;
    const int row0 = blockIdx.x * 128;
    const int mrow = wm * 32;
    const int ncol = wn * 64;

    // A load coords: 4 float4 per thread (128 rows x 32 k fp32 per tile)
    int lr[4], lc[4];
#pragma unroll
    for (int i = 0; i < 4; i++) {
        int idx = tid + i * 256;
        lr[i] = idx >> 3;        // row 0..127
        lc[i] = (idx & 7) * 4;   // k offset 0..28
    }
    // B load coords: 2 x 16B chunks per thread (128 n x 32 k fp16 = 8KB)
    int bn[2], bc[2];
#pragma unroll
    for (int i = 0; i < 2; i++) {
        int idx = tid + i * 256;
        bn[i] = idx >> 2;        // n 0..127
        bc[i] = (idx & 3) * 8;   // k offset in halves 0,8,16,24
    }

    auto load_b = [&](int stage, int k0) {
        __half* Bd = BH + stage * B_TILE_H;
#pragma unroll
        for (int i = 0; i < 2; i++) {
            const __half* src = g_Wth + (size_t)bn[i] * D_IN + k0 + bc[i];
            cp_async16(smem_u32(Bd + bn[i] * APAD + bc[i]), src, 16);
        }
        cp_commit();
    };

    auto load_a_regs = [&](int k0, float4* pre) {
#pragma unroll
        for (int i = 0; i < 4; i++) {
            int gr = row0 + lr[i];
            pre[i] = (gr < M)
                ? *reinterpret_cast<const float4*>(A + (size_t)gr * D_IN + k0 + lc[i])
                : make_float4(0.f, 0.f, 0.f, 0.f);
        }
    };

    float c[2][8][4];
#pragma unroll
    for (int mt = 0; mt < 2; mt++)
#pragma unroll
        for (int nt = 0; nt < 8; nt++)
#pragma unroll
            for (int i = 0; i < 4; i++) c[mt][nt][i] = 0.f;

    float4 pre[4];
    load_a_regs(0, pre);
    load_b(0, 0);
    load_b(1, 32);

    for (int kt = 0; kt < NKT; kt++) {
        const int s = kt & 1;
        // store prefetched A (converted to fp16) into stage s.
        // Safe: stage s was last READ at iter kt-2; every warp passed the
        // barrier of iter kt-1 only after finishing those reads.
        __half* Ad = AH + s * A_TILE_H;
#pragma unroll
        for (int i = 0; i < 4; i++) {
            uint2 v;
            v.x = f16x2_rn(pre[i].x, pre[i].y);
            v.y = f16x2_rn(pre[i].z, pre[i].w);
            *reinterpret_cast<uint2*>(Ad + lr[i] * APAD + lc[i]) = v;
        }
        // prefetch next A tile into regs (latency hidden by compute below)
        if (kt + 1 < NKT) load_a_regs((kt + 1) * 32, pre);

        if (kt + 2 < NKT) { cp_wait<1>(); } else { cp_wait<0>(); }
        __syncthreads();                       // single barrier per k-tile
        if (kt + 2 < NKT) load_b((kt + 2) % 3, (kt + 2) * 32);

        const __half* As = AH + s * A_TILE_H;
        const __half* Bt = BH + (kt % 3) * B_TILE_H;

#pragma unroll
        for (int ks = 0; ks < 32; ks += 16) {
            uint32_t a[2][4];
#pragma unroll
            for (int mt = 0; mt < 2; mt++) {
                uint32_t addr = smem_u32(
                    As + (mrow + mt * 16 + (lane & 7) + 8 * ((lane >> 3) & 1)) * APAD
                       + ks + 8 * (lane >> 4));
                ldsm_x4(a[mt][0], a[mt][1], a[mt][2], a[mt][3], addr);
            }
            uint32_t b[8][2];
#pragma unroll
            for (int p = 0; p < 4; p++) {
                uint32_t r0, r1, r2, r3;
                uint32_t addr = smem_u32(
                    Bt + (ncol + p * 16 + (lane & 7) + 8 * ((lane >> 3) & 1)) * APAD
                       + ks + 8 * (lane >> 4));
                ldsm_x4(r0, r1, r2, r3, addr);
                b[2 * p][0]     = r0; b[2 * p][1]     = r2;
                b[2 * p + 1][0] = r1; b[2 * p + 1][1] = r3;
            }
#pragma unroll
            for (int mt = 0; mt < 2; mt++)
#pragma unroll
                for (int nt = 0; nt < 8; nt++)
                    mma_f16(c[mt][nt], a[mt], b[nt][0], b[nt][1]);
        }
    }

    // ---------------- epilogue: fp16 h store + a1/a2 via smem exchange ------
    __syncthreads();    // guard smem reuse (all warps done reading tiles)
    float* sp1 = reinterpret_cast<float*>(smh);         // [128]
    float* sp2 = reinterpret_cast<float*>(smh) + 128;   // [128]

    const float ba1v = ba1[0];
    const float ba2v = ba2[0];
    const int qrow = lane >> 2;
    const int qcol = 2 * (lane & 3);

    float P1[2][2], P2[2][2];   // [mt][lo/hi]

#pragma unroll
    for (int mt = 0; mt < 2; mt++) {
        int grlo = row0 + mrow + mt * 16 + qrow;
        int grhi = grlo + 8;
        float p1lo = 0.f, p2lo = 0.f, p1hi = 0.f, p2hi = 0.f;
#pragma unroll
        for (int nt = 0; nt < 8; nt++) {
            int gc = ncol + nt * 8 + qcol;
            float bc0 = bias[gc], bc1 = bias[gc + 1];
            float v0 = c[mt][nt][0] + bc0;
            float v1 = c[mt][nt][1] + bc1;
            float v2 = c[mt][nt][2] + bc0;
            float v3 = c[mt][nt][3] + bc1;
            if (grlo < M)
                g_hh[(size_t)grlo * (D_OUT / 2) + gc / 2] = f16x2_rn(v0, v1);
            if (grhi < M)
                g_hh[(size_t)grhi * (D_OUT / 2) + gc / 2] = f16x2_rn(v2, v3);
            float w1a = wa1[gc], w1b = wa1[gc + 1];
            float w2a = wa2[gc], w2b = wa2[gc + 1];
            p1lo += v0 * w1a + v1 * w1b;
            p2lo += v0 * w2a + v1 * w2b;
            p1hi += v2 * w1a + v3 * w1b;
            p2hi += v2 * w2a + v3 * w2b;
        }
#pragma unroll
        for (int o = 1; o < 4; o <<= 1) {
            p1lo += __shfl_xor_sync(0xffffffffu, p1lo, o);
            p2lo += __shfl_xor_sync(0xffffffffu, p2lo, o);
            p1hi += __shfl_xor_sync(0xffffffffu, p1hi, o);
            p2hi += __shfl_xor_sync(0xffffffffu, p2hi, o);
        }
        P1[mt][0] = p1lo; P1[mt][1] = p1hi;
        P2[mt][0] = p2lo; P2[mt][1] = p2hi;
    }

    // wn=1 publishes partials; wn=0 combines and stores (no atomics)
    if (wn == 1 && (lane & 3) == 0) {
#pragma unroll
        for (int mt = 0; mt < 2; mt++) {
            int lrow = mrow + mt * 16 + qrow;
            sp1[lrow]     = P1[mt][0];  sp2[lrow]     = P2[mt][0];
            sp1[lrow + 8] = P1[mt][1];  sp2[lrow + 8] = P2[mt][1];
        }
    }
    __syncthreads();
    if (wn == 0 && (lane & 3) == 0) {
#pragma unroll
        for (int mt = 0; mt < 2; mt++) {
            int lrow = mrow + mt * 16 + qrow;
            int grlo = row0 + lrow, grhi = grlo + 8;
            if (grlo < M) {
                g_a1[grlo] = P1[mt][0] + sp1[lrow] + ba1v;
                g_a2[grlo] = P2[mt][0] + sp2[lrow] + ba2v;
            }
            if (grhi < M) {
                g_a1[grhi] = P1[mt][1] + sp1[lrow + 8] + ba1v;
                g_a2[grhi] = P2[mt][1] + sp2[lrow + 8] + ba2v;
            }
        }
    }
}

// ---------------- histogram of destination rows (also zeros g_bsum) ---------
__global__ void __launch_bounds__(256) hist_kernel(
    const int* __restrict__ row, int E)
{
    if (blockIdx.x == 0 && threadIdx.x < 128)
        g_bsum[threadIdx.x] = 0;

    int t = blockIdx.x * blockDim.x + threadIdx.x;
    int nq = E >> 2;
    if (t < nq) {
        int4 v = reinterpret_cast<const int4*>(row)[t];
        atomicAdd(&g_count[v.x], 1);
        atomicAdd(&g_count[v.y], 1);
        atomicAdd(&g_count[v.z], 1);
        atomicAdd(&g_count[v.w], 1);
    }
    int rem = nq * 4 + t;
    if (t < (E & 3) && rem < E) atomicAdd(&g_count[row[rem]], 1);
}

// ---------------- fused single-pass exclusive scan (inter-block lookback) ----
__device__ __forceinline__ void block_scan_1024(int v, int tid, int& excl, int& total)
{
    int lane = tid & 31, wid = tid >> 5;
    int x = v;
#pragma unroll
    for (int o = 1; o < 32; o <<= 1) {
        int y = __shfl_up_sync(0xffffffffu, x, o);
        if (lane >= o) x += y;
    }
    __shared__ int ws[32];
    if (lane == 31) ws[wid] = x;
    __syncthreads();
    if (wid == 0) {
        int s = ws[lane];
#pragma unroll
        for (int o = 1; o < 32; o <<= 1) {
            int y = __shfl_up_sync(0xffffffffu, s, o);
            if (lane >= o) s += y;
        }
        ws[lane] = s;
    }
    __syncthreads();
    int warp_off = (wid > 0) ? ws[wid - 1] : 0;
    int incl = warp_off + x;
    excl  = incl - v;
    total = ws[31];
}

__global__ void __launch_bounds__(SCAN_BLK) scan_fused_kernel(int n, int E)
{
    int i = blockIdx.x * SCAN_BLK + threadIdx.x;
    int v = (i < n) ? g_count[i] : 0;
    int excl, total;
    block_scan_1024(v, threadIdx.x, excl, total);

    if (threadIdx.x == 0)
        atomicExch(&g_bsum[blockIdx.x], (unsigned)total | VALID_FLAG);

    int part = 0;
    if (threadIdx.x < blockIdx.x) {
        unsigned w;
        do { w = atomicAdd(&g_bsum[threadIdx.x], 0u); } while (!(w & VALID_FLAG));
        part = (int)(w & (VALID_FLAG - 1));
    }
    int lane = threadIdx.x & 31, wid = threadIdx.x >> 5;
#pragma unroll
    for (int o = 16; o > 0; o >>= 1)
        part += __shfl_xor_sync(0xffffffffu, part, o);
    __shared__ int rs[32];
    __syncthreads();
    if (lane == 0) rs[wid] = part;
    __syncthreads();
    if (wid == 0) {
        int s = rs[lane];
#pragma unroll
        for (int o = 16; o > 0; o >>= 1)
            s += __shfl_xor_sync(0xffffffffu, s, o);
        rs[0] = s;
    }
    __syncthreads();
    int offset = rs[0];

    if (i < n) {
        int vv = excl + offset;
        g_rowstart[i] = vv;
        g_pos[i]      = vv;
        if (i == n - 1) g_rowstart[n] = E;
    }
}

// ---------------- CSR (row,col) scatter — NO scores, runs in fork -----------
__global__ void __launch_bounds__(256) scatter_rc_kernel(
    const int* __restrict__ row, const int* __restrict__ col, int E)
{
    int e = blockIdx.x * blockDim.x + threadIdx.x;
    if (e < E) {
        int r = row[e];
        int p = atomicAdd(&g_pos[r], 1);
        g_src[p] = make_int2(r, col[e]);
    }
}

// ---------------- score pass: coalesced, 2 edges per thread -----------------
__global__ void __launch_bounds__(256) score_kernel(int E)
{
    int t = blockIdx.x * blockDim.x + threadIdx.x;
    int p = t * 2;
    if (p + 1 < E) {
        int4 rc2 = *reinterpret_cast<const int4*>(g_src + p);  // two int2
        float s0 = g_a1[rc2.x] + g_a2[rc2.y];
        float s1 = g_a1[rc2.z] + g_a2[rc2.w];
        s0 = (s0 > 0.f) ? s0 : 0.01f * s0;
        s1 = (s1 > 0.f) ? s1 : 0.01f * s1;
        float4 o;
        o.x = __int_as_float(rc2.y);  o.y = __expf(s0);
        o.z = __int_as_float(rc2.w);  o.w = __expf(s1);
        *reinterpret_cast<float4*>(g_scw + p) = o;
    } else if (p < E) {
        int2 rc = g_src[p];
        float s = g_a1[rc.x] + g_a2[rc.y];
        s = (s > 0.f) ? s : 0.01f * s;
        g_scw[p] = make_float2(__int_as_float(rc.y), __expf(s));
    }
}

// ---------------- CSR gather SpMM: one warp per row, fp16 h ----------------
__device__ __forceinline__ void f16x2_unpack(uint32_t u, float& lo, float& hi) {
    __half2 h = *reinterpret_cast<__half2*>(&u);
    float2 f = __half22float2(h);
    lo = f.x;
    hi = f.y;
}

__global__ void __launch_bounds__(256) spmm_csr_kernel(
    float* __restrict__ out, int M)
{
    int r    = (blockIdx.x * blockDim.x + threadIdx.x) >> 5;
    int lane = threadIdx.x & 31;
    if (r >= M) return;

    int start = g_rowstart[r];
    int end   = g_rowstart[r + 1];

    float4 acc = make_float4(0.f, 0.f, 0.f, 0.f);

    if (end > start) {
        const uint2* __restrict__ h2 = reinterpret_cast<const uint2*>(g_hh);
        float dsum = 0.f;   // identical in every lane

        for (int base = start; base < end; base += 32) {
            int   i = base + lane;
            int   cc = 0;
            float ww = 0.f;
            if (i < end) {
                float2 e = g_scw[i];
                cc = __float_as_int(e.x);
                ww = e.y;
            }
            int n = end - base; if (n > 32) n = 32;

            int j = 0;
            for (; j + 4 <= n; j += 4) {
                int   c0 = __shfl_sync(0xffffffffu, cc, j);
                int   c1 = __shfl_sync(0xffffffffu, cc, j + 1);
                int   c2 = __shfl_sync(0xffffffffu, cc, j + 2);
                int   c3 = __shfl_sync(0xffffffffu, cc, j + 3);
                float w0 = __shfl_sync(0xffffffffu, ww, j);
                float w1 = __shfl_sync(0xffffffffu, ww, j + 1);
                float w2 = __shfl_sync(0xffffffffu, ww, j + 2);
                float w3 = __shfl_sync(0xffffffffu, ww, j + 3);
                uint2 u0 = h2[(size_t)c0 * 32 + lane];
                uint2 u1 = h2[(size_t)c1 * 32 + lane];
                uint2 u2 = h2[(size_t)c2 * 32 + lane];
                uint2 u3 = h2[(size_t)c3 * 32 + lane];
                dsum += w0 + w1 + w2 + w3;
                float ax, ay, az, aw;
                f16x2_unpack(u0.x, ax, ay); f16x2_unpack(u0.y, az, aw);
                acc.x = fmaf(w0, ax, acc.x); acc.y = fmaf(w0, ay, acc.y);
                acc.z = fmaf(w0, az, acc.z); acc.w = fmaf(w0, aw, acc.w);
                f16x2_unpack(u1.x, ax, ay); f16x2_unpack(u1.y, az, aw);
                acc.x = fmaf(w1, ax, acc.x); acc.y = fmaf(w1, ay, acc.y);
                acc.z = fmaf(w1, az, acc.z); acc.w = fmaf(w1, aw, acc.w);
                f16x2_unpack(u2.x, ax, ay); f16x2_unpack(u2.y, az, aw);
                acc.x = fmaf(w2, ax, acc.x); acc.y = fmaf(w2, ay, acc.y);
                acc.z = fmaf(w2, az, acc.z); acc.w = fmaf(w2, aw, acc.w);
                f16x2_unpack(u3.x, ax, ay); f16x2_unpack(u3.y, az, aw);
                acc.x = fmaf(w3, ax, acc.x); acc.y = fmaf(w3, ay, acc.y);
                acc.z = fmaf(w3, az, acc.z); acc.w = fmaf(w3, aw, acc.w);
            }
            for (; j < n; j++) {
                int   cj = __shfl_sync(0xffffffffu, cc, j);
                float wj = __shfl_sync(0xffffffffu, ww, j);
                uint2 u = h2[(size_t)cj * 32 + lane];
                dsum += wj;
                float ax, ay, az, aw;
                f16x2_unpack(u.x, ax, ay); f16x2_unpack(u.y, az, aw);
                acc.x = fmaf(wj, ax, acc.x); acc.y = fmaf(wj, ay, acc.y);
                acc.z = fmaf(wj, az, acc.z); acc.w = fmaf(wj, aw, acc.w);
            }
        }
        float inv = 1.0f / dsum;
        acc.x *= inv; acc.y *= inv; acc.z *= inv; acc.w *= inv;
    }
    *reinterpret_cast<float4*>(out + (size_t)r * D_OUT + lane * 4) = acc;
}

// ---------------- launch: fork starts immediately; transpose on main --------
extern "C" void kernel_launch(void* const* d_in, const int* in_sizes, int n_in,
                              void* d_out, int out_size)
{
    const float* features = (const float*)d_in[0];
    const int*   ei       = (const int*)d_in[1];
    const float* W        = (const float*)d_in[2];
    const float* b        = (const float*)d_in[3];
    const float* wa1      = (const float*)d_in[4];
    const float* ba1      = (const float*)d_in[5];
    const float* wa2      = (const float*)d_in[6];
    const float* ba2      = (const float*)d_in[7];

    const int M = in_sizes[0] / D_IN;   // 100000
    const int E = in_sizes[1] / 2;      // 1600000
    float* out = (float*)d_out;

    const int* rowp = ei;
    const int* colp = ei + E;

    // lazily created once on the (uncaptured) correctness call; reused during capture
    static cudaStream_t s1 = nullptr;
    static cudaEvent_t  evFork = nullptr, evJoin = nullptr;
    if (s1 == nullptr) {
        cudaStreamCreateWithFlags(&s1, cudaStreamNonBlocking);
        cudaEventCreateWithFlags(&evFork, cudaEventDisableTiming);
        cudaEventCreateWithFlags(&evJoin, cudaEventDisableTiming);
    }

    void* p = nullptr;

    // fork FIRST: s1 must not wait on the transpose
    cudaEventRecord(evFork, 0);
    cudaStreamWaitEvent(s1, evFork, 0);

    // s1: CSR structure build (independent of GEMM, low bandwidth)
    cudaGetSymbolAddress(&p, g_count);
    cudaMemsetAsync(p, 0, (size_t)M * sizeof(int), s1);
    hist_kernel<<<(E / 4 + 255) / 256, 256, 0, s1>>>(rowp, E);  // also zeros g_bsum
    int nb = (M + SCAN_BLK - 1) / SCAN_BLK;
    scan_fused_kernel<<<nb, SCAN_BLK, 0, s1>>>(M, E);
    int eblocks = (E + 255) / 256;
    scatter_rc_kernel<<<eblocks, 256, 0, s1>>>(rowp, colp, E);
    cudaEventRecord(evJoin, s1);

    // main stream: W transpose + GEMM (writes a1/a2 directly)
    transpose_w_kernel<<<(D_IN * D_OUT + 255) / 256, 256>>>(W);

    static const size_t smem_bytes = (2 * A_TILE_H + 3 * B_TILE_H) * sizeof(__half); // 51200
    cudaFuncSetAttribute(gemm_f16_kernel,
                         cudaFuncAttributeMaxDynamicSharedMemorySize,
                         (int)smem_bytes);
    int gblocks = (M + 127) / 128;
    gemm_f16_kernel<<<gblocks, 256, smem_bytes>>>(features, b, wa1, wa2, ba1, ba2, M);

    // join: score needs g_src (s1) + a1/a2 (main)
    cudaStreamWaitEvent(0, evJoin, 0);

    int sblocks = (E / 2 + 255) / 256;
    score_kernel<<<sblocks, 256>>>(E);

    long long total_threads = (long long)M * 32;
    int mblocks = (int)((total_threads + 255) / 256);
    spmm_csr_kernel<<<mblocks, 256>>>(out, M);
}